// round 2
// baseline (speedup 1.0000x reference)
#include <cuda_runtime.h>
#include <math.h>

#define Bsz 2
#define T 2048
#define Cdim 2048
#define H 16
#define D 128
#define BH (Bsz * H)
#define EPSV 1.1920929e-07f

// ---------------- scratch (static device allocations only) ----------------
__device__ float g_qkv[(size_t)Bsz * T * 3 * Cdim];   // 100 MB
__device__ float g_q[(size_t)BH * T * D];             // 32 MB  [bh][t][d]
__device__ float g_k[(size_t)BH * T * D];             // 32 MB
__device__ float g_v[(size_t)BH * T * D];             // 32 MB
__device__ float g_s[(size_t)BH * T * T];             // 512 MB (S, then P in-place)
__device__ float g_y[(size_t)Bsz * T * Cdim];         // 32 MB
__device__ float g_cos[T * 64];
__device__ float g_sin[T * 64];

// ---------------- RoPE tables (double precision, tiny) ----------------
__global__ void rope_tables_kernel() {
    int t = blockIdx.x;
    int j = threadIdx.x;  // 0..63
    double inv = exp(-((double)j / 64.0) * 13.815510557964274);  // ln(1e6)
    double a = (double)t * inv;
    g_cos[t * 64 + j] = (float)cos(a);
    g_sin[t * 64 + j] = (float)sin(a);
}

// ---------------- generic SGEMM: C[M,N] = A[M,K] @ B[K,N] ----------------
// 128x128 tile, BK=8, 256 threads, 8x8 micro-tile. Dims multiples of tile.
__global__ __launch_bounds__(256, 2)
void sgemm_kernel(const float* __restrict__ A, const float* __restrict__ B,
                  float* __restrict__ C, int K, int lda, int ldb, int ldc)
{
    __shared__ float As[8][128];
    __shared__ float Bs[8][128];
    const int row0 = blockIdx.y * 128;
    const int col0 = blockIdx.x * 128;
    const int tid = threadIdx.x;
    const int tx = tid & 15;
    const int ty = tid >> 4;
    const int a_row = tid >> 1;
    const int a_col = (tid & 1) << 2;
    const int b_row = tid >> 5;
    const int b_col = (tid & 31) << 2;
    const float* Ap = A + (size_t)(row0 + a_row) * lda + a_col;
    const float* Bp = B + (size_t)b_row * ldb + col0 + b_col;

    float acc[8][8];
#pragma unroll
    for (int i = 0; i < 8; i++)
#pragma unroll
        for (int j = 0; j < 8; j++) acc[i][j] = 0.f;

    for (int k0 = 0; k0 < K; k0 += 8) {
        float4 av = *(const float4*)(Ap + k0);
        float4 bv = *(const float4*)(Bp + (size_t)k0 * ldb);
        __syncthreads();
        As[a_col + 0][a_row] = av.x;
        As[a_col + 1][a_row] = av.y;
        As[a_col + 2][a_row] = av.z;
        As[a_col + 3][a_row] = av.w;
        *(float4*)&Bs[b_row][b_col] = bv;
        __syncthreads();
#pragma unroll
        for (int kk = 0; kk < 8; kk++) {
            float a[8], b[8];
            *(float4*)(a)     = *(const float4*)&As[kk][ty << 3];
            *(float4*)(a + 4) = *(const float4*)&As[kk][(ty << 3) + 4];
            *(float4*)(b)     = *(const float4*)&Bs[kk][tx << 3];
            *(float4*)(b + 4) = *(const float4*)&Bs[kk][(tx << 3) + 4];
#pragma unroll
            for (int i = 0; i < 8; i++)
#pragma unroll
                for (int j = 0; j < 8; j++)
                    acc[i][j] = fmaf(a[i], b[j], acc[i][j]);
        }
    }
#pragma unroll
    for (int i = 0; i < 8; i++) {
        float* Cp = C + (size_t)(row0 + (ty << 3) + i) * ldc + col0 + (tx << 3);
        *(float4*)(Cp)     = make_float4(acc[i][0], acc[i][1], acc[i][2], acc[i][3]);
        *(float4*)(Cp + 4) = make_float4(acc[i][4], acc[i][5], acc[i][6], acc[i][7]);
    }
}

// ---------------- RMSNorm + RoPE + scatter ----------------
__global__ __launch_bounds__(128)
void qkv_post_kernel(const float* __restrict__ qw, const float* __restrict__ kw)
{
    const int bt = blockIdx.x;          // b*T + t
    const int h  = blockIdx.y;
    const int d  = threadIdx.x;         // 0..127
    const int t  = bt & (T - 1);
    const int b  = bt >> 11;            // T = 2048
    const float* base = g_qkv + (size_t)bt * (3 * Cdim);
    float qv = base[h * D + d];
    float kv = base[Cdim + h * D + d];
    float vv = base[2 * Cdim + h * D + d];

    float q2 = qv * qv, k2 = kv * kv;
#pragma unroll
    for (int off = 16; off; off >>= 1) {
        q2 += __shfl_xor_sync(0xffffffffu, q2, off);
        k2 += __shfl_xor_sync(0xffffffffu, k2, off);
    }
    __shared__ float rq[4], rk[4];
    if ((d & 31) == 0) { rq[d >> 5] = q2; rk[d >> 5] = k2; }
    __syncthreads();
    float qms = (rq[0] + rq[1] + rq[2] + rq[3]) * (1.f / D);
    float kms = (rk[0] + rk[1] + rk[2] + rk[3]) * (1.f / D);
    float qn = qv * rsqrtf(qms + EPSV) * qw[d];
    float kn = kv * rsqrtf(kms + EPSV) * kw[d];

    __shared__ float sq[128], sk[128];
    sq[d] = qn; sk[d] = kn;
    __syncthreads();
    int j = d & 63;
    float c = g_cos[t * 64 + j];
    float s = g_sin[t * 64 + j];
    float qo, ko;
    if (d < 64) { qo = qn * c - sq[d + 64] * s; ko = kn * c - sk[d + 64] * s; }
    else        { qo = qn * c + sq[d - 64] * s; ko = kn * c + sk[d - 64] * s; }

    const size_t o = (((size_t)(b * H + h)) * T + t) * D + d;
    g_q[o] = qo; g_k[o] = ko; g_v[o] = vv;
}

// ---------------- S = Q @ K^T (batched over bh, causal tile skip) ----------------
__global__ __launch_bounds__(256, 2)
void attn_s_kernel()
{
    const int kt = blockIdx.x;
    const int qt = blockIdx.y;
    if (kt > qt) return;                // fully-masked tile
    const int bh = blockIdx.z;
    const float* Q  = g_q + (size_t)bh * T * D;
    const float* Km = g_k + (size_t)bh * T * D;
    float* S = g_s + (size_t)bh * T * T;

    __shared__ float As[8][128];
    __shared__ float Bs[8][128];
    const int row0 = qt * 128;
    const int col0 = kt * 128;
    const int tid = threadIdx.x;
    const int tx = tid & 15;
    const int ty = tid >> 4;
    const int a_row = tid >> 1;
    const int a_col = (tid & 1) << 2;
    const int b_row = tid >> 5;
    const int b_col = (tid & 31) << 2;
    const float* Ap = Q + (size_t)(row0 + a_row) * D + a_col;

    float acc[8][8];
#pragma unroll
    for (int i = 0; i < 8; i++)
#pragma unroll
        for (int j = 0; j < 8; j++) acc[i][j] = 0.f;

    for (int k0 = 0; k0 < D; k0 += 8) {
        float4 av = *(const float4*)(Ap + k0);
        float bvals[4];
#pragma unroll
        for (int i = 0; i < 4; i++)
            bvals[i] = Km[(size_t)(col0 + b_col + i) * D + k0 + b_row];
        __syncthreads();
        As[a_col + 0][a_row] = av.x;
        As[a_col + 1][a_row] = av.y;
        As[a_col + 2][a_row] = av.z;
        As[a_col + 3][a_row] = av.w;
#pragma unroll
        for (int i = 0; i < 4; i++) Bs[b_row][b_col + i] = bvals[i];
        __syncthreads();
#pragma unroll
        for (int kk = 0; kk < 8; kk++) {
            float a[8], b[8];
            *(float4*)(a)     = *(const float4*)&As[kk][ty << 3];
            *(float4*)(a + 4) = *(const float4*)&As[kk][(ty << 3) + 4];
            *(float4*)(b)     = *(const float4*)&Bs[kk][tx << 3];
            *(float4*)(b + 4) = *(const float4*)&Bs[kk][(tx << 3) + 4];
#pragma unroll
            for (int i = 0; i < 8; i++)
#pragma unroll
                for (int j = 0; j < 8; j++)
                    acc[i][j] = fmaf(a[i], b[j], acc[i][j]);
        }
    }
#pragma unroll
    for (int i = 0; i < 8; i++) {
        float* Sp = S + (size_t)(row0 + (ty << 3) + i) * T + col0 + (tx << 3);
        *(float4*)(Sp)     = make_float4(acc[i][0], acc[i][1], acc[i][2], acc[i][3]);
        *(float4*)(Sp + 4) = make_float4(acc[i][4], acc[i][5], acc[i][6], acc[i][7]);
    }
}

// ---------------- causal softmax (in place, scale 1/D) ----------------
__global__ __launch_bounds__(256)
void softmax_kernel()
{
    const int row = blockIdx.x;          // bh*T + q
    const int q = row & (T - 1);
    float* Srow = g_s + (size_t)row * T;
    const int tid = threadIdx.x;
    const float scale = 1.0f / (float)D;

    float v[8];
    float m = -3.4e38f;
#pragma unroll
    for (int i = 0; i < 8; i++) {
        int j = (i << 8) + tid;
        float s = (j <= q) ? Srow[j] * scale : -INFINITY;
        v[i] = s;
        m = fmaxf(m, s);
    }
#pragma unroll
    for (int off = 16; off; off >>= 1)
        m = fmaxf(m, __shfl_xor_sync(0xffffffffu, m, off));
    __shared__ float redm[8], reds[8];
    if ((tid & 31) == 0) redm[tid >> 5] = m;
    __syncthreads();
    float bm = redm[0];
#pragma unroll
    for (int w = 1; w < 8; w++) bm = fmaxf(bm, redm[w]);

    float sum = 0.f;
#pragma unroll
    for (int i = 0; i < 8; i++) {
        float p = expf(v[i] - bm);   // masked: exp(-inf) = 0
        v[i] = p;
        sum += p;
    }
#pragma unroll
    for (int off = 16; off; off >>= 1)
        sum += __shfl_xor_sync(0xffffffffu, sum, off);
    if ((tid & 31) == 0) reds[tid >> 5] = sum;
    __syncthreads();
    float bs = reds[0];
#pragma unroll
    for (int w = 1; w < 8; w++) bs += reds[w];
    float inv = 1.0f / bs;
#pragma unroll
    for (int i = 0; i < 8; i++)
        Srow[(i << 8) + tid] = v[i] * inv;
}

// ---------------- Y = P @ V, written into [B,T,C] layout ----------------
__global__ __launch_bounds__(256, 2)
void attn_y_kernel()
{
    const int qt = blockIdx.y;
    const int bh = blockIdx.z;
    const float* P = g_s + (size_t)bh * T * T;
    const float* V = g_v + (size_t)bh * T * D;
    const int b = bh >> 4;               // H = 16
    const int h = bh & 15;
    float* Cbase = g_y + (size_t)b * T * Cdim + h * D;

    __shared__ float As[8][128];
    __shared__ float Bs[8][128];
    const int row0 = qt * 128;
    const int Kmax = (qt + 1) * 128;     // causal K bound
    const int tid = threadIdx.x;
    const int tx = tid & 15;
    const int ty = tid >> 4;
    const int a_row = tid >> 1;
    const int a_col = (tid & 1) << 2;
    const int b_row = tid >> 5;
    const int b_col = (tid & 31) << 2;
    const float* Ap = P + (size_t)(row0 + a_row) * T + a_col;
    const float* Bp = V + (size_t)b_row * D + b_col;

    float acc[8][8];
#pragma unroll
    for (int i = 0; i < 8; i++)
#pragma unroll
        for (int j = 0; j < 8; j++) acc[i][j] = 0.f;

    for (int k0 = 0; k0 < Kmax; k0 += 8) {
        float4 av = *(const float4*)(Ap + k0);
        float4 bv = *(const float4*)(Bp + (size_t)k0 * D);
        __syncthreads();
        As[a_col + 0][a_row] = av.x;
        As[a_col + 1][a_row] = av.y;
        As[a_col + 2][a_row] = av.z;
        As[a_col + 3][a_row] = av.w;
        *(float4*)&Bs[b_row][b_col] = bv;
        __syncthreads();
#pragma unroll
        for (int kk = 0; kk < 8; kk++) {
            float a[8], b[8];
            *(float4*)(a)     = *(const float4*)&As[kk][ty << 3];
            *(float4*)(a + 4) = *(const float4*)&As[kk][(ty << 3) + 4];
            *(float4*)(b)     = *(const float4*)&Bs[kk][tx << 3];
            *(float4*)(b + 4) = *(const float4*)&Bs[kk][(tx << 3) + 4];
#pragma unroll
            for (int i = 0; i < 8; i++)
#pragma unroll
                for (int j = 0; j < 8; j++)
                    acc[i][j] = fmaf(a[i], b[j], acc[i][j]);
        }
    }
#pragma unroll
    for (int i = 0; i < 8; i++) {
        float* Cp = Cbase + (size_t)(row0 + (ty << 3) + i) * Cdim + (tx << 3);
        *(float4*)(Cp)     = make_float4(acc[i][0], acc[i][1], acc[i][2], acc[i][3]);
        *(float4*)(Cp + 4) = make_float4(acc[i][4], acc[i][5], acc[i][6], acc[i][7]);
    }
}

// ---------------- launcher ----------------
extern "C" void kernel_launch(void* const* d_in, const int* in_sizes, int n_in,
                              void* d_out, int out_size)
{
    const float* x      = (const float*)d_in[0];
    const float* w_qkv  = (const float*)d_in[1];
    const float* w_proj = (const float*)d_in[2];
    const float* qw     = (const float*)d_in[3];
    const float* kw     = (const float*)d_in[4];
    float* out = (float*)d_out;

    float *p_qkv = nullptr, *p_y = nullptr;
    cudaGetSymbolAddress((void**)&p_qkv, g_qkv);
    cudaGetSymbolAddress((void**)&p_y, g_y);

    // 1. RoPE tables
    rope_tables_kernel<<<T, 64>>>();
    // 2. qkv = x @ w_qkv   (M=4096, N=6144, K=2048)
    sgemm_kernel<<<dim3(3 * Cdim / 128, (Bsz * T) / 128), 256>>>(
        x, w_qkv, p_qkv, Cdim, Cdim, 3 * Cdim, 3 * Cdim);
    // 3. RMSNorm + RoPE + scatter into [BH,T,D]
    qkv_post_kernel<<<dim3(Bsz * T, H), 128>>>(qw, kw);
    // 4. S = Q @ K^T (causal tile skip)
    attn_s_kernel<<<dim3(T / 128, T / 128, BH), 256>>>();
    // 5. causal softmax (scale 1/D), in-place S -> P
    softmax_kernel<<<BH * T, 256>>>();
    // 6. Y = P @ V written to [B,T,C]
    attn_y_kernel<<<dim3(1, T / 128, BH), 256>>>();
    // 7. out = y @ w_proj  (M=4096, N=2048, K=2048)
    sgemm_kernel<<<dim3(Cdim / 128, (Bsz * T) / 128), 256>>>(
        p_y, w_proj, out, Cdim, Cdim, Cdim, Cdim);
}

// round 3
// speedup vs baseline: 1.7240x; 1.7240x over previous
#include <cuda_runtime.h>
#include <math.h>
#include <stdint.h>

#define Bsz 2
#define T 2048
#define Cdim 2048
#define H 16
#define D 128
#define BH (Bsz * H)
#define EPSV 1.1920929e-07f

// ---------------- scratch (static device allocations only) ----------------
__device__ __align__(128) float g_qkv[(size_t)Bsz * T * 3 * Cdim];   // 100 MB
__device__ __align__(128) float g_q[(size_t)BH * T * D];             // 32 MB
__device__ __align__(128) float g_k[(size_t)BH * T * D];             // 32 MB
__device__ __align__(128) float g_v[(size_t)BH * T * D];             // 32 MB
__device__ __align__(128) float g_s[(size_t)BH * T * T];             // 512 MB
__device__ __align__(128) float g_y[(size_t)Bsz * T * Cdim];         // 32 MB
__device__ __align__(128) float g_cos[T * 64];
__device__ __align__(128) float g_sin[T * 64];

// ---------------- helpers ----------------
__device__ __forceinline__ uint32_t f2tf(float f) {
    uint32_t u;
    asm("cvt.rna.tf32.f32 %0, %1;" : "=r"(u) : "f"(f));
    return u;
}

__device__ __forceinline__ void mma_tf32(float* d, const uint32_t* a,
                                         uint32_t b0, uint32_t b1) {
    asm volatile(
        "mma.sync.aligned.m16n8k8.row.col.f32.tf32.tf32.f32 "
        "{%0,%1,%2,%3}, {%4,%5,%6,%7}, {%8,%9}, {%0,%1,%2,%3};\n"
        : "+f"(d[0]), "+f"(d[1]), "+f"(d[2]), "+f"(d[3])
        : "r"(a[0]), "r"(a[1]), "r"(a[2]), "r"(a[3]), "r"(b0), "r"(b1));
}

// ---------------- RoPE tables ----------------
__global__ void rope_tables_kernel() {
    int t = blockIdx.x;
    int j = threadIdx.x;  // 0..63
    double inv = exp(-((double)j / 64.0) * 13.815510557964274);  // ln(1e6)
    double a = (double)t * inv;
    g_cos[t * 64 + j] = (float)cos(a);
    g_sin[t * 64 + j] = (float)sin(a);
}

// ---------------- TF32 MMA tile core ----------------
// Block tile 128x128, BK=16, 256 threads = 8 warps of 32x64 warp-tiles.
// Smem layout (per k-step slab of 8 ks): idx = m*10 + (k&3)*2 + (k>>2), so
// each fragment is one aligned LDS.64. Slab stride = 1280 u32.
// BT=false: B is [K,N] row-major (ldb = row stride).
// BT=true : B is [N,K] row-major (ldb = row stride) -> computes A @ B^T.
template <bool BT>
__device__ __forceinline__ void mma_tile(
    const float* __restrict__ A, int lda,
    const float* __restrict__ B, int ldb,
    float* __restrict__ C, int ldc,
    int K, int row0, int col0)
{
    __shared__ uint32_t As[2 * 1280];
    __shared__ uint32_t Bs[2 * 1280];

    const int tid  = threadIdx.x;
    const int warp = tid >> 5;
    const int lane = tid & 31;
    const int g = lane >> 2;       // 0..7
    const int c = lane & 3;        // 0..3
    const int wm = (warp >> 1) * 32;
    const int wn = (warp & 1) * 64;

    // A gmem mapping: row = tid>>1 (0..127), k offset = (tid&1)*8
    const int a_row = tid >> 1;
    const int a_kc  = (tid & 1) << 3;
    const float* Ap = A + (size_t)(row0 + a_row) * lda + a_kc;
    // A smem store base: slab = (tid&1)
    uint32_t* As_st = As + (tid & 1) * 1280 + a_row * 10;

    // B gmem mapping
    const float* Bp;
    uint32_t* Bs_st;
    int b_coff = 0;
    if (BT) {
        // read rows of B[N,K]: n = tid>>1, k offset = (tid&1)*8
        const int n  = tid >> 1;
        const int kc = (tid & 1) << 3;
        Bp = B + (size_t)(col0 + n) * ldb + kc;
        Bs_st = Bs + (tid & 1) * 1280 + n * 10;
    } else {
        // read rows of B[K,N]: k = tid>>4 (0..15), n offset = (tid&15)*8
        const int kr = tid >> 4;
        const int nc = (tid & 15) << 3;
        Bp = B + (size_t)kr * ldb + col0 + nc;
        const int kk = kr & 7;
        b_coff = ((kk & 3) << 1) + (kk >> 2);
        Bs_st = Bs + (kr >> 3) * 1280 + nc * 10;
    }

    float acc[2][8][4];
#pragma unroll
    for (int i = 0; i < 2; i++)
#pragma unroll
        for (int j = 0; j < 8; j++)
#pragma unroll
            for (int r = 0; r < 4; r++) acc[i][j][r] = 0.f;

    // interleave permutation for 8 consecutive k values
    const int kperm[8] = {0, 2, 4, 6, 1, 3, 5, 7};

    for (int k0 = 0; k0 < K; k0 += 16) {
        // stage gmem
        float4 av0 = *(const float4*)(Ap + k0);
        float4 av1 = *(const float4*)(Ap + k0 + 4);
        float4 bv0, bv1;
        if (BT) {
            bv0 = *(const float4*)(Bp + k0);
            bv1 = *(const float4*)(Bp + k0 + 4);
        } else {
            bv0 = *(const float4*)(Bp + (size_t)k0 * ldb);
            bv1 = *(const float4*)(Bp + (size_t)k0 * ldb + 4);
        }
        __syncthreads();
        {
            float av[8] = {av0.x, av0.y, av0.z, av0.w, av1.x, av1.y, av1.z, av1.w};
#pragma unroll
            for (int t2 = 0; t2 < 8; t2++) As_st[kperm[t2]] = f2tf(av[t2]);
            float bvv[8] = {bv0.x, bv0.y, bv0.z, bv0.w, bv1.x, bv1.y, bv1.z, bv1.w};
            if (BT) {
#pragma unroll
                for (int t2 = 0; t2 < 8; t2++) Bs_st[kperm[t2]] = f2tf(bvv[t2]);
            } else {
#pragma unroll
                for (int t2 = 0; t2 < 8; t2++) Bs_st[t2 * 10 + b_coff] = f2tf(bvv[t2]);
            }
        }
        __syncthreads();

#pragma unroll
        for (int ks = 0; ks < 2; ks++) {
            const uint32_t* as = As + ks * 1280;
            const uint32_t* bs = Bs + ks * 1280;
            uint32_t a[2][4];
#pragma unroll
            for (int i = 0; i < 2; i++) {
                int r = wm + i * 16 + g;
                uint2 lo = *(const uint2*)&as[r * 10 + c * 2];
                uint2 hi = *(const uint2*)&as[(r + 8) * 10 + c * 2];
                a[i][0] = lo.x; a[i][1] = hi.x; a[i][2] = lo.y; a[i][3] = hi.y;
            }
#pragma unroll
            for (int j = 0; j < 8; j++) {
                int n = wn + j * 8 + g;
                uint2 bb = *(const uint2*)&bs[n * 10 + c * 2];
#pragma unroll
                for (int i = 0; i < 2; i++)
                    mma_tf32(acc[i][j], a[i], bb.x, bb.y);
            }
        }
    }

    // epilogue: c0,c1 -> (row g, cols 2c,2c+1); c2,c3 -> (row g+8)
#pragma unroll
    for (int i = 0; i < 2; i++) {
        int r0 = row0 + wm + i * 16 + g;
#pragma unroll
        for (int j = 0; j < 8; j++) {
            int col = col0 + wn + j * 8 + c * 2;
            *(float2*)&C[(size_t)r0 * ldc + col] = make_float2(acc[i][j][0], acc[i][j][1]);
            *(float2*)&C[(size_t)(r0 + 8) * ldc + col] = make_float2(acc[i][j][2], acc[i][j][3]);
        }
    }
}

// ---------------- GEMM wrappers ----------------
__global__ __launch_bounds__(256, 2)
void gemm_tf32_kernel(const float* __restrict__ A, const float* __restrict__ B,
                      float* __restrict__ C, int K, int lda, int ldb, int ldc)
{
    mma_tile<false>(A, lda, B, ldb, C, ldc, K, blockIdx.y * 128, blockIdx.x * 128);
}

__global__ __launch_bounds__(256, 2)
void attn_s_kernel()
{
    const int kt = blockIdx.x;
    const int qt = blockIdx.y;
    if (kt > qt) return;
    const int bh = blockIdx.z;
    mma_tile<true>(g_q + (size_t)bh * T * D, D,
                   g_k + (size_t)bh * T * D, D,
                   g_s + (size_t)bh * T * T, T,
                   D, qt * 128, kt * 128);
}

__global__ __launch_bounds__(256, 2)
void attn_y_kernel()
{
    const int qt = blockIdx.y;
    const int bh = blockIdx.z;
    const int b = bh >> 4;
    const int h = bh & 15;
    mma_tile<false>(g_s + (size_t)bh * T * T, T,
                    g_v + (size_t)bh * T * D, D,
                    g_y + (size_t)b * T * Cdim + h * D, Cdim,
                    (qt + 1) * 128, qt * 128, 0);
}

// ---------------- RMSNorm + RoPE + scatter ----------------
__global__ __launch_bounds__(128)
void qkv_post_kernel(const float* __restrict__ qw, const float* __restrict__ kw)
{
    const int bt = blockIdx.x;
    const int h  = blockIdx.y;
    const int d  = threadIdx.x;
    const int t  = bt & (T - 1);
    const int b  = bt >> 11;
    const float* base = g_qkv + (size_t)bt * (3 * Cdim);
    float qv = base[h * D + d];
    float kv = base[Cdim + h * D + d];
    float vv = base[2 * Cdim + h * D + d];

    float q2 = qv * qv, k2 = kv * kv;
#pragma unroll
    for (int off = 16; off; off >>= 1) {
        q2 += __shfl_xor_sync(0xffffffffu, q2, off);
        k2 += __shfl_xor_sync(0xffffffffu, k2, off);
    }
    __shared__ float rq[4], rk[4];
    if ((d & 31) == 0) { rq[d >> 5] = q2; rk[d >> 5] = k2; }
    __syncthreads();
    float qms = (rq[0] + rq[1] + rq[2] + rq[3]) * (1.f / D);
    float kms = (rk[0] + rk[1] + rk[2] + rk[3]) * (1.f / D);
    float qn = qv * rsqrtf(qms + EPSV) * qw[d];
    float kn = kv * rsqrtf(kms + EPSV) * kw[d];

    __shared__ float sq[128], sk[128];
    sq[d] = qn; sk[d] = kn;
    __syncthreads();
    int j = d & 63;
    float cc = g_cos[t * 64 + j];
    float ss = g_sin[t * 64 + j];
    float qo, ko;
    if (d < 64) { qo = qn * cc - sq[d + 64] * ss; ko = kn * cc - sk[d + 64] * ss; }
    else        { qo = qn * cc + sq[d - 64] * ss; ko = kn * cc + sk[d - 64] * ss; }

    const size_t o = (((size_t)(b * H + h)) * T + t) * D + d;
    g_q[o] = qo; g_k[o] = ko; g_v[o] = vv;
}

// ---------------- causal softmax (bounded, in place, scale 1/D) ----------------
__global__ __launch_bounds__(256)
void softmax_kernel()
{
    const int row = blockIdx.x;          // bh*T + q
    const int q = row & (T - 1);
    float* Srow = g_s + (size_t)row * T;
    const int tid = threadIdx.x;
    const float scale = 1.0f / (float)D;
    const int nt = (q >> 8) + 1;         // 256-wide chunks needed

    float v[8];
    float m = -3.4e38f;
#pragma unroll
    for (int i = 0; i < 8; i++) {
        if (i >= nt) break;
        int j = (i << 8) + tid;
        float s = (j <= q) ? Srow[j] * scale : -INFINITY;
        v[i] = s;
        m = fmaxf(m, s);
    }
#pragma unroll
    for (int off = 16; off; off >>= 1)
        m = fmaxf(m, __shfl_xor_sync(0xffffffffu, m, off));
    __shared__ float redm[8], reds[8];
    if ((tid & 31) == 0) redm[tid >> 5] = m;
    __syncthreads();
    float bm = redm[0];
#pragma unroll
    for (int w = 1; w < 8; w++) bm = fmaxf(bm, redm[w]);

    float sum = 0.f;
#pragma unroll
    for (int i = 0; i < 8; i++) {
        if (i >= nt) break;
        float p = expf(v[i] - bm);
        v[i] = p;
        sum += p;
    }
#pragma unroll
    for (int off = 16; off; off >>= 1)
        sum += __shfl_xor_sync(0xffffffffu, sum, off);
    if ((tid & 31) == 0) reds[tid >> 5] = sum;
    __syncthreads();
    float bs = reds[0];
#pragma unroll
    for (int w = 1; w < 8; w++) bs += reds[w];
    float inv = 1.0f / bs;
#pragma unroll
    for (int i = 0; i < 8; i++) {
        if (i >= nt) break;
        Srow[(i << 8) + tid] = v[i] * inv;
    }
}

// ---------------- launcher ----------------
extern "C" void kernel_launch(void* const* d_in, const int* in_sizes, int n_in,
                              void* d_out, int out_size)
{
    const float* x      = (const float*)d_in[0];
    const float* w_qkv  = (const float*)d_in[1];
    const float* w_proj = (const float*)d_in[2];
    const float* qw     = (const float*)d_in[3];
    const float* kw     = (const float*)d_in[4];
    float* out = (float*)d_out;

    float *p_qkv = nullptr, *p_y = nullptr;
    cudaGetSymbolAddress((void**)&p_qkv, g_qkv);
    cudaGetSymbolAddress((void**)&p_y, g_y);

    // 1. RoPE tables
    rope_tables_kernel<<<T, 64>>>();
    // 2. qkv = x @ w_qkv   (M=4096, N=6144, K=2048)
    gemm_tf32_kernel<<<dim3(3 * Cdim / 128, (Bsz * T) / 128), 256>>>(
        x, w_qkv, p_qkv, Cdim, Cdim, 3 * Cdim, 3 * Cdim);
    // 3. RMSNorm + RoPE + scatter into [BH,T,D]
    qkv_post_kernel<<<dim3(Bsz * T, H), 128>>>(qw, kw);
    // 4. S = Q @ K^T (causal tile skip)
    attn_s_kernel<<<dim3(T / 128, T / 128, BH), 256>>>();
    // 5. causal softmax (scale 1/D), in-place S -> P
    softmax_kernel<<<BH * T, 256>>>();
    // 6. Y = P @ V written to [B,T,C]
    attn_y_kernel<<<dim3(1, T / 128, BH), 256>>>();
    // 7. out = y @ w_proj  (M=4096, N=2048, K=2048)
    gemm_tf32_kernel<<<dim3(Cdim / 128, (Bsz * T) / 128), 256>>>(
        p_y, w_proj, out, Cdim, Cdim, Cdim, Cdim);
}

// round 4
// speedup vs baseline: 1.7296x; 1.0033x over previous
#include <cuda_runtime.h>
#include <math.h>
#include <stdint.h>

#define Bsz 2
#define T 2048
#define Cdim 2048
#define H 16
#define D 128
#define BH (Bsz * H)
#define EPSV 1.1920929e-07f

// ---------------- scratch (static device allocations only) ----------------
__device__ __align__(128) float g_qkv[(size_t)Bsz * T * 3 * Cdim];   // 100 MB
__device__ __align__(128) float g_q[(size_t)BH * T * D];             // 32 MB
__device__ __align__(128) float g_k[(size_t)BH * T * D];             // 32 MB
__device__ __align__(128) float g_v[(size_t)BH * T * D];             // 32 MB
__device__ __align__(128) float g_s[(size_t)BH * T * T];             // 512 MB
__device__ __align__(128) float g_y[(size_t)Bsz * T * Cdim];         // 32 MB
__device__ __align__(128) float g_cos[T * 64];
__device__ __align__(128) float g_sin[T * 64];

// ---------------- helpers ----------------
__device__ __forceinline__ uint32_t f2tf(float f) {
    uint32_t u;
    asm("cvt.rna.tf32.f32 %0, %1;" : "=r"(u) : "f"(f));
    return u;
}

__device__ __forceinline__ void mma_tf32(float* d, const uint32_t* a,
                                         uint32_t b0, uint32_t b1) {
    asm volatile(
        "mma.sync.aligned.m16n8k8.row.col.f32.tf32.tf32.f32 "
        "{%0,%1,%2,%3}, {%4,%5,%6,%7}, {%8,%9}, {%0,%1,%2,%3};\n"
        : "+f"(d[0]), "+f"(d[1]), "+f"(d[2]), "+f"(d[3])
        : "r"(a[0]), "r"(a[1]), "r"(a[2]), "r"(a[3]), "r"(b0), "r"(b1));
}

// ---------------- RoPE tables ----------------
__global__ void rope_tables_kernel() {
    int t = blockIdx.x;
    int j = threadIdx.x;  // 0..63
    double inv = exp(-((double)j / 64.0) * 13.815510557964274);  // ln(1e6)
    double a = (double)t * inv;
    g_cos[t * 64 + j] = (float)cos(a);
    g_sin[t * 64 + j] = (float)sin(a);
}

// ---------------- TF32 MMA tile core ----------------
// Block tile 128x128, BK=16, 256 threads = 8 warps of 32x64 warp-tiles.
// Smem layout (per k-step slab of 8 ks): idx = m*10 + (k&3)*2 + (k>>2), so
// each fragment is one aligned LDS.64. Slab stride = 1280 u32.
// BT=false: B is [K,N] row-major (ldb = row stride).
// BT=true : B is [N,K] row-major (ldb = row stride) -> computes A @ B^T.
template <bool BT>
__device__ __forceinline__ void mma_tile(
    const float* __restrict__ A, int lda,
    const float* __restrict__ B, int ldb,
    float* __restrict__ C, int ldc,
    int K, int row0, int col0)
{
    __shared__ uint32_t As[2 * 1280];
    __shared__ uint32_t Bs[2 * 1280];

    const int tid  = threadIdx.x;
    const int warp = tid >> 5;
    const int lane = tid & 31;
    const int g = lane >> 2;       // 0..7
    const int c = lane & 3;        // 0..3
    const int wm = (warp >> 1) * 32;
    const int wn = (warp & 1) * 64;

    // A gmem mapping: row = tid>>1 (0..127), k offset = (tid&1)*8
    const int a_row = tid >> 1;
    const int a_kc  = (tid & 1) << 3;
    const float* Ap = A + (size_t)(row0 + a_row) * lda + a_kc;
    // A smem store base: slab = (tid&1)
    uint32_t* As_st = As + (tid & 1) * 1280 + a_row * 10;

    // B gmem mapping
    const float* Bp;
    uint32_t* Bs_st;
    int b_coff = 0;
    if (BT) {
        // read rows of B[N,K]: n = tid>>1, k offset = (tid&1)*8
        const int n  = tid >> 1;
        const int kc = (tid & 1) << 3;
        Bp = B + (size_t)(col0 + n) * ldb + kc;
        Bs_st = Bs + (tid & 1) * 1280 + n * 10;
    } else {
        // read rows of B[K,N]: k = tid>>4 (0..15), n offset = (tid&15)*8
        const int kr = tid >> 4;
        const int nc = (tid & 15) << 3;
        Bp = B + (size_t)kr * ldb + col0 + nc;
        const int kk = kr & 7;
        b_coff = ((kk & 3) << 1) + (kk >> 2);
        Bs_st = Bs + (kr >> 3) * 1280 + nc * 10;
    }

    float acc[2][8][4];
#pragma unroll
    for (int i = 0; i < 2; i++)
#pragma unroll
        for (int j = 0; j < 8; j++)
#pragma unroll
            for (int r = 0; r < 4; r++) acc[i][j][r] = 0.f;

    // interleave permutation for 8 consecutive k values
    const int kperm[8] = {0, 2, 4, 6, 1, 3, 5, 7};

    for (int k0 = 0; k0 < K; k0 += 16) {
        // stage gmem
        float4 av0 = *(const float4*)(Ap + k0);
        float4 av1 = *(const float4*)(Ap + k0 + 4);
        float4 bv0, bv1;
        if (BT) {
            bv0 = *(const float4*)(Bp + k0);
            bv1 = *(const float4*)(Bp + k0 + 4);
        } else {
            bv0 = *(const float4*)(Bp + (size_t)k0 * ldb);
            bv1 = *(const float4*)(Bp + (size_t)k0 * ldb + 4);
        }
        __syncthreads();
        {
            float av[8] = {av0.x, av0.y, av0.z, av0.w, av1.x, av1.y, av1.z, av1.w};
#pragma unroll
            for (int t2 = 0; t2 < 8; t2++) As_st[kperm[t2]] = f2tf(av[t2]);
            float bvv[8] = {bv0.x, bv0.y, bv0.z, bv0.w, bv1.x, bv1.y, bv1.z, bv1.w};
            if (BT) {
#pragma unroll
                for (int t2 = 0; t2 < 8; t2++) Bs_st[kperm[t2]] = f2tf(bvv[t2]);
            } else {
#pragma unroll
                for (int t2 = 0; t2 < 8; t2++) Bs_st[t2 * 10 + b_coff] = f2tf(bvv[t2]);
            }
        }
        __syncthreads();

#pragma unroll
        for (int ks = 0; ks < 2; ks++) {
            const uint32_t* as = As + ks * 1280;
            const uint32_t* bs = Bs + ks * 1280;
            uint32_t a[2][4];
#pragma unroll
            for (int i = 0; i < 2; i++) {
                int r = wm + i * 16 + g;
                uint2 lo = *(const uint2*)&as[r * 10 + c * 2];
                uint2 hi = *(const uint2*)&as[(r + 8) * 10 + c * 2];
                a[i][0] = lo.x; a[i][1] = hi.x; a[i][2] = lo.y; a[i][3] = hi.y;
            }
#pragma unroll
            for (int j = 0; j < 8; j++) {
                int n = wn + j * 8 + g;
                uint2 bb = *(const uint2*)&bs[n * 10 + c * 2];
#pragma unroll
                for (int i = 0; i < 2; i++)
                    mma_tf32(acc[i][j], a[i], bb.x, bb.y);
            }
        }
    }

    // epilogue: c0,c1 -> (row g, cols 2c,2c+1); c2,c3 -> (row g+8)
#pragma unroll
    for (int i = 0; i < 2; i++) {
        int r0 = row0 + wm + i * 16 + g;
#pragma unroll
        for (int j = 0; j < 8; j++) {
            int col = col0 + wn + j * 8 + c * 2;
            *(float2*)&C[(size_t)r0 * ldc + col] = make_float2(acc[i][j][0], acc[i][j][1]);
            *(float2*)&C[(size_t)(r0 + 8) * ldc + col] = make_float2(acc[i][j][2], acc[i][j][3]);
        }
    }
}

// ---------------- GEMM wrappers ----------------
__global__ __launch_bounds__(256, 2)
void gemm_tf32_kernel(const float* __restrict__ A, const float* __restrict__ B,
                      float* __restrict__ C, int K, int lda, int ldb, int ldc)
{
    mma_tile<false>(A, lda, B, ldb, C, ldc, K, blockIdx.y * 128, blockIdx.x * 128);
}

__global__ __launch_bounds__(256, 2)
void attn_s_kernel()
{
    const int kt = blockIdx.x;
    const int qt = blockIdx.y;
    if (kt > qt) return;
    const int bh = blockIdx.z;
    mma_tile<true>(g_q + (size_t)bh * T * D, D,
                   g_k + (size_t)bh * T * D, D,
                   g_s + (size_t)bh * T * T, T,
                   D, qt * 128, kt * 128);
}

__global__ __launch_bounds__(256, 2)
void attn_y_kernel()
{
    const int qt = blockIdx.y;
    const int bh = blockIdx.z;
    const int b = bh >> 4;
    const int h = bh & 15;
    mma_tile<false>(g_s + (size_t)bh * T * T, T,
                    g_v + (size_t)bh * T * D, D,
                    g_y + (size_t)b * T * Cdim + h * D, Cdim,
                    (qt + 1) * 128, qt * 128, 0);
}

// ---------------- RMSNorm + RoPE + scatter ----------------
__global__ __launch_bounds__(128)
void qkv_post_kernel(const float* __restrict__ qw, const float* __restrict__ kw)
{
    const int bt = blockIdx.x;
    const int h  = blockIdx.y;
    const int d  = threadIdx.x;
    const int t  = bt & (T - 1);
    const int b  = bt >> 11;
    const float* base = g_qkv + (size_t)bt * (3 * Cdim);
    float qv = base[h * D + d];
    float kv = base[Cdim + h * D + d];
    float vv = base[2 * Cdim + h * D + d];

    float q2 = qv * qv, k2 = kv * kv;
#pragma unroll
    for (int off = 16; off; off >>= 1) {
        q2 += __shfl_xor_sync(0xffffffffu, q2, off);
        k2 += __shfl_xor_sync(0xffffffffu, k2, off);
    }
    __shared__ float rq[4], rk[4];
    if ((d & 31) == 0) { rq[d >> 5] = q2; rk[d >> 5] = k2; }
    __syncthreads();
    float qms = (rq[0] + rq[1] + rq[2] + rq[3]) * (1.f / D);
    float kms = (rk[0] + rk[1] + rk[2] + rk[3]) * (1.f / D);
    float qn = qv * rsqrtf(qms + EPSV) * qw[d];
    float kn = kv * rsqrtf(kms + EPSV) * kw[d];

    __shared__ float sq[128], sk[128];
    sq[d] = qn; sk[d] = kn;
    __syncthreads();
    int j = d & 63;
    float cc = g_cos[t * 64 + j];
    float ss = g_sin[t * 64 + j];
    float qo, ko;
    if (d < 64) { qo = qn * cc - sq[d + 64] * ss; ko = kn * cc - sk[d + 64] * ss; }
    else        { qo = qn * cc + sq[d - 64] * ss; ko = kn * cc + sk[d - 64] * ss; }

    const size_t o = (((size_t)(b * H + h)) * T + t) * D + d;
    g_q[o] = qo; g_k[o] = ko; g_v[o] = vv;
}

// ---------------- causal softmax (bounded, in place, scale 1/D) ----------------
__global__ __launch_bounds__(256)
void softmax_kernel()
{
    const int row = blockIdx.x;          // bh*T + q
    const int q = row & (T - 1);
    float* Srow = g_s + (size_t)row * T;
    const int tid = threadIdx.x;
    const float scale = 1.0f / (float)D;
    const int nt = (q >> 8) + 1;         // 256-wide chunks needed

    float v[8];
    float m = -3.4e38f;
#pragma unroll
    for (int i = 0; i < 8; i++) {
        if (i >= nt) break;
        int j = (i << 8) + tid;
        float s = (j <= q) ? Srow[j] * scale : -INFINITY;
        v[i] = s;
        m = fmaxf(m, s);
    }
#pragma unroll
    for (int off = 16; off; off >>= 1)
        m = fmaxf(m, __shfl_xor_sync(0xffffffffu, m, off));
    __shared__ float redm[8], reds[8];
    if ((tid & 31) == 0) redm[tid >> 5] = m;
    __syncthreads();
    float bm = redm[0];
#pragma unroll
    for (int w = 1; w < 8; w++) bm = fmaxf(bm, redm[w]);

    float sum = 0.f;
#pragma unroll
    for (int i = 0; i < 8; i++) {
        if (i >= nt) break;
        float p = expf(v[i] - bm);
        v[i] = p;
        sum += p;
    }
#pragma unroll
    for (int off = 16; off; off >>= 1)
        sum += __shfl_xor_sync(0xffffffffu, sum, off);
    if ((tid & 31) == 0) reds[tid >> 5] = sum;
    __syncthreads();
    float bs = reds[0];
#pragma unroll
    for (int w = 1; w < 8; w++) bs += reds[w];
    float inv = 1.0f / bs;
#pragma unroll
    for (int i = 0; i < 8; i++) {
        if (i >= nt) break;
        Srow[(i << 8) + tid] = v[i] * inv;
    }
}

// ---------------- launcher ----------------
extern "C" void kernel_launch(void* const* d_in, const int* in_sizes, int n_in,
                              void* d_out, int out_size)
{
    const float* x      = (const float*)d_in[0];
    const float* w_qkv  = (const float*)d_in[1];
    const float* w_proj = (const float*)d_in[2];
    const float* qw     = (const float*)d_in[3];
    const float* kw     = (const float*)d_in[4];
    float* out = (float*)d_out;

    float *p_qkv = nullptr, *p_y = nullptr;
    cudaGetSymbolAddress((void**)&p_qkv, g_qkv);
    cudaGetSymbolAddress((void**)&p_y, g_y);

    // 1. RoPE tables
    rope_tables_kernel<<<T, 64>>>();
    // 2. qkv = x @ w_qkv   (M=4096, N=6144, K=2048)
    gemm_tf32_kernel<<<dim3(3 * Cdim / 128, (Bsz * T) / 128), 256>>>(
        x, w_qkv, p_qkv, Cdim, Cdim, 3 * Cdim, 3 * Cdim);
    // 3. RMSNorm + RoPE + scatter into [BH,T,D]
    qkv_post_kernel<<<dim3(Bsz * T, H), 128>>>(qw, kw);
    // 4. S = Q @ K^T (causal tile skip)
    attn_s_kernel<<<dim3(T / 128, T / 128, BH), 256>>>();
    // 5. causal softmax (scale 1/D), in-place S -> P
    softmax_kernel<<<BH * T, 256>>>();
    // 6. Y = P @ V written to [B,T,C]
    attn_y_kernel<<<dim3(1, T / 128, BH), 256>>>();
    // 7. out = y @ w_proj  (M=4096, N=2048, K=2048)
    gemm_tf32_kernel<<<dim3(Cdim / 128, (Bsz * T) / 128), 256>>>(
        p_y, w_proj, out, Cdim, Cdim, Cdim, Cdim);
}